// round 2
// baseline (speedup 1.0000x reference)
#include <cuda_runtime.h>

#define BB 256
#define TT 1024
#define HH 64
#define GG 256   // 4*H gates

// Inter-layer activations (ping-pong). 2 x 64 MB device globals (no allocs).
__device__ float g_bufA[BB * TT * HH];
__device__ float g_bufB[BB * TT * HH];

typedef unsigned long long ull;

__device__ __forceinline__ float sigf(float x) {
    x = fminf(fmaxf(x, -30.f), 30.f);
    return 1.0f / (1.0f + __expf(-x));
}
__device__ __forceinline__ float tanhf_fast(float x) {
    x = fminf(fmaxf(x, -15.f), 15.f);
    float e = __expf(-2.0f * x);
    return (1.0f - e) / (1.0f + e);
}

// Blackwell packed fp32 ops — only reachable via PTX.
#define FFMA2(acc, a, b) \
    asm("fma.rn.f32x2 %0, %1, %2, %0;" : "+l"(acc) : "l"(a), "l"(b))
#define ADD2(d, a, b) \
    asm("add.rn.f32x2 %0, %1, %2;" : "=l"(d) : "l"(a), "l"(b))
#define UNPACK2(lo, hi, p) \
    asm("mov.b64 {%0,%1}, %2;" : "=f"(lo), "=f"(hi) : "l"(p))
#define PACK2(p, lo, hi) \
    asm("mov.b64 %0, {%1,%2};" : "=l"(p) : "f"(lo), "f"(hi))

// One LSTM layer scan. 128 CTAs x 256 threads; CTA owns 2 batch rows.
// Thread g owns gate-row g; W_ih/W_hh rows live in registers (packed f32x2).
// Per step:  phaseA: h-part FMA (4 chains) + combine + nonlin + gsm store
//            sync
//            phaseB: state update (g<128)  ||  x-part FMA for t+1 (all)  || x prefetch
//            sync
template <bool FIRST>
__global__ void __launch_bounds__(256, 1)
lstm_scan(const float* __restrict__ xin,   // FIRST: [B,T,1] else [B,T,64]
          const float* __restrict__ wih,   // FIRST: [256,1] else [256,64]
          const float* __restrict__ whh,   // [256,64]
          const float* __restrict__ bih,   // [256]
          const float* __restrict__ bhh,   // [256]
          float* __restrict__ hout)        // [B,T,64]
{
    const int g  = threadIdx.x;
    const int b0 = blockIdx.x * 2;
    const int bb = g >> 6;      // batch (valid when g<128)
    const int jj = g & 63;      // unit

    __shared__ __align__(16) float hs[2][64];
    __shared__ __align__(16) float xs[2][2][64];  // [parity][batch][j]; x_t lives in xs[t&1]
    __shared__ float gsm[2][256];

    // ---- weights into registers (packed f32x2 pairs; rows are 256B-aligned) ----
    ull whh2[32];
    ull wih2[32];
    float wih0s = 0.f;
    if (FIRST) {
        wih0s = wih[g];
    } else {
        const ull* wr = reinterpret_cast<const ull*>(wih + g * 64);
        #pragma unroll
        for (int k = 0; k < 32; k++) wih2[k] = wr[k];
    }
    {
        const ull* wr = reinterpret_cast<const ull*>(whh + g * 64);
        #pragma unroll
        for (int k = 0; k < 32; k++) whh2[k] = wr[k];
    }
    const float bsum = bih[g] + bhh[g];

    // ---- prologue: h=0, stage x0 -> xs[0], x1 -> xs[1] ----
    if (g < 128) {
        hs[bb][jj] = 0.f;
        if (FIRST) {
            if (jj == 0) {
                xs[0][bb][0] = xin[(b0 + bb) * TT + 0];
                xs[1][bb][0] = xin[(b0 + bb) * TT + 1];
            }
        } else {
            xs[0][bb][jj] = xin[((size_t)(b0 + bb) * TT + 0) * 64 + jj];
            xs[1][bb][jj] = xin[((size_t)(b0 + bb) * TT + 1) * 64 + jj];
        }
    }
    __syncthreads();

    // carried x-part partials (batch0: xp0,xp1; batch1: xq0,xq1) or scalars for FIRST
    ull xp0 = 0, xp1 = 0, xq0 = 0, xq1 = 0;
    float xf0 = 0.f, xf1 = 0.f;

#define XACC_COMPUTE(PAR)                                                     \
    do {                                                                      \
        if (FIRST) {                                                          \
            xf0 = wih0s * xs[PAR][0][0];                                      \
            xf1 = wih0s * xs[PAR][1][0];                                      \
        } else {                                                              \
            xp0 = 0; xp1 = 0; xq0 = 0; xq1 = 0;                               \
            const ulonglong2* x0 = reinterpret_cast<const ulonglong2*>(xs[PAR][0]); \
            const ulonglong2* x1 = reinterpret_cast<const ulonglong2*>(xs[PAR][1]); \
            _Pragma("unroll")                                                 \
            for (int k = 0; k < 8; k++) {                                     \
                ulonglong2 va = x0[2 * k];                                    \
                ulonglong2 vb = x0[2 * k + 1];                                \
                ulonglong2 vc = x1[2 * k];                                    \
                ulonglong2 vd = x1[2 * k + 1];                                \
                FFMA2(xp0, wih2[4 * k],     va.x);                            \
                FFMA2(xp1, wih2[4 * k + 1], va.y);                            \
                FFMA2(xp0, wih2[4 * k + 2], vb.x);                            \
                FFMA2(xp1, wih2[4 * k + 3], vb.y);                            \
                FFMA2(xq0, wih2[4 * k],     vc.x);                            \
                FFMA2(xq1, wih2[4 * k + 1], vc.y);                            \
                FFMA2(xq0, wih2[4 * k + 2], vd.x);                            \
                FFMA2(xq1, wih2[4 * k + 3], vd.y);                            \
            }                                                                 \
        }                                                                     \
    } while (0)

    XACC_COMPUTE(0);  // x-part for t=0

    // prefetch x_2 into a register (consumed in phase B of t=0)
    float xnext = 0.f;
    if (g < 128) {
        if (FIRST) { if (jj == 0) xnext = xin[(b0 + bb) * TT + 2]; }
        else       { xnext = xin[((size_t)(b0 + bb) * TT + 2) * 64 + jj]; }
    }
    float c = 0.f;

    for (int t = 0; t < TT; ++t) {
        // ---------------- phase A: h-part + combine + nonlinearity ----------------
        ull hp0 = 0, hp1 = 0, hp2 = 0, hp3 = 0;   // batch0, 4 chains (depth 8)
        ull hq0 = 0, hq1 = 0, hq2 = 0, hq3 = 0;   // batch1
        {
            const ulonglong2* h0 = reinterpret_cast<const ulonglong2*>(hs[0]);
            const ulonglong2* h1 = reinterpret_cast<const ulonglong2*>(hs[1]);
            #pragma unroll
            for (int k = 0; k < 8; k++) {
                ulonglong2 va = h0[2 * k];
                ulonglong2 vb = h0[2 * k + 1];
                ulonglong2 vc = h1[2 * k];
                ulonglong2 vd = h1[2 * k + 1];
                FFMA2(hp0, whh2[4 * k],     va.x);
                FFMA2(hp1, whh2[4 * k + 1], va.y);
                FFMA2(hp2, whh2[4 * k + 2], vb.x);
                FFMA2(hp3, whh2[4 * k + 3], vb.y);
                FFMA2(hq0, whh2[4 * k],     vc.x);
                FFMA2(hq1, whh2[4 * k + 1], vc.y);
                FFMA2(hq2, whh2[4 * k + 2], vd.x);
                FFMA2(hq3, whh2[4 * k + 3], vd.y);
            }
        }
        float a0, a1;
        {
            ull u, v;
            ADD2(u, hp0, hp1); ADD2(v, hp2, hp3); ADD2(u, u, v);
            if (!FIRST) { ull w; ADD2(w, xp0, xp1); ADD2(u, u, w); }
            float lo, hi; UNPACK2(lo, hi, u);
            a0 = bsum + lo + hi;
            ADD2(u, hq0, hq1); ADD2(v, hq2, hq3); ADD2(u, u, v);
            if (!FIRST) { ull w; ADD2(w, xq0, xq1); ADD2(u, u, w); }
            UNPACK2(lo, hi, u);
            a1 = bsum + lo + hi;
            if (FIRST) { a0 += xf0; a1 += xf1; }
        }
        // gate order i,f,g,o: rows [128,192) use tanh
        float v0, v1;
        if ((g >> 6) == 2) { v0 = tanhf_fast(a0); v1 = tanhf_fast(a1); }
        else               { v0 = sigf(a0);       v1 = sigf(a1); }
        gsm[0][g] = v0;
        gsm[1][g] = v1;
        __syncthreads();

        // ---------------- phase B: update || x-part(t+1) || prefetch ----------------
        if (g < 128) {
            float iv = gsm[bb][jj];
            float fv = gsm[bb][64 + jj];
            float gv = gsm[bb][128 + jj];
            float ov = gsm[bb][192 + jj];
            c = fv * c + iv * gv;
            float hval = ov * tanhf_fast(c);
            hs[bb][jj] = hval;
            hout[(((size_t)(b0 + bb)) * TT + t) * 64 + jj] = hval;
            if (t + 2 < TT) {  // stage x_{t+2} into xs[t&1]
                if (FIRST) { if (jj == 0) xs[t & 1][bb][0] = xnext; }
                else       { xs[t & 1][bb][jj] = xnext; }
            }
        }
        // x-part for step t+1 (reads xs[(t+1)&1], staged two iterations ago)
        XACC_COMPUTE((t + 1) & 1);
        // prefetch x_{t+3}
        if (g < 128 && t + 3 < TT) {
            if (FIRST) { if (jj == 0) xnext = xin[(b0 + bb) * TT + t + 3]; }
            else       { xnext = xin[((size_t)(b0 + bb) * TT + t + 3) * 64 + jj]; }
        }
        __syncthreads();
    }
#undef XACC_COMPUTE
}

// Head: out = relu(relu(h) @ W1^T + b1) @ W2^T + b2.
// Warp handles 2 positions; packed weight pairs (j, j+32) -> FFMA2.
__global__ void __launch_bounds__(256)
fc_kernel(const float* __restrict__ hin,  // [B,T,64]
          const float* __restrict__ W1,   // [64,64]
          const float* __restrict__ b1,   // [64]
          const float* __restrict__ W2,   // [1,64]
          const float* __restrict__ b2,   // [1]
          float* __restrict__ out)        // [B*T]
{
    __shared__ ull  W1P[64 * 32];   // W1P[k*32+l] = (W1[l][k], W1[l+32][k]), 16KB
    __shared__ float b1s[64];
    __shared__ float w2s[64];
    __shared__ float hsm[8][2][64];

    for (int i = threadIdx.x; i < 64 * 32; i += 256) {
        int k = i >> 5, l = i & 31;
        ull p; PACK2(p, W1[l * 64 + k], W1[(l + 32) * 64 + k]);
        W1P[k * 32 + l] = p;
    }
    if (threadIdx.x < 64) {
        b1s[threadIdx.x] = b1[threadIdx.x];
        w2s[threadIdx.x] = W2[threadIdx.x];
    }
    __syncthreads();
    const float b2v = b2[0];

    const int warp = threadIdx.x >> 5, lane = threadIdx.x & 31;
    ull ybias; PACK2(ybias, b1s[lane], b1s[lane + 32]);
    const float w2lo = w2s[lane], w2hi = w2s[lane + 32];

    const int npairs = BB * TT / 2;
    for (int pair = blockIdx.x * 8 + warp; pair < npairs; pair += gridDim.x * 8) {
        size_t p0 = (size_t)pair * 2;
        float h00 = fmaxf(hin[p0 * 64 + lane], 0.f);
        float h01 = fmaxf(hin[p0 * 64 + 32 + lane], 0.f);
        float h10 = fmaxf(hin[(p0 + 1) * 64 + lane], 0.f);
        float h11 = fmaxf(hin[(p0 + 1) * 64 + 32 + lane], 0.f);
        hsm[warp][0][lane]      = h00;
        hsm[warp][0][lane + 32] = h01;
        hsm[warp][1][lane]      = h10;
        hsm[warp][1][lane + 32] = h11;
        __syncwarp();

        ull y0a = ybias, y0b = 0, y1a = ybias, y1b = 0;
        #pragma unroll
        for (int k = 0; k < 64; k += 2) {
            ull w0 = W1P[k * 32 + lane];
            ull w1 = W1P[(k + 1) * 32 + lane];
            float hv00 = hsm[warp][0][k],     hv01 = hsm[warp][0][k + 1];
            float hv10 = hsm[warp][1][k],     hv11 = hsm[warp][1][k + 1];
            ull d00; PACK2(d00, hv00, hv00);
            ull d01; PACK2(d01, hv01, hv01);
            ull d10; PACK2(d10, hv10, hv10);
            ull d11; PACK2(d11, hv11, hv11);
            FFMA2(y0a, w0, d00);
            FFMA2(y0b, w1, d01);
            FFMA2(y1a, w0, d10);
            FFMA2(y1b, w1, d11);
        }
        ADD2(y0a, y0a, y0b);
        ADD2(y1a, y1a, y1b);
        float u0, u1, v0, v1;
        UNPACK2(u0, u1, y0a);
        UNPACK2(v0, v1, y1a);
        float part0 = fmaxf(u0, 0.f) * w2lo + fmaxf(u1, 0.f) * w2hi;
        float part1 = fmaxf(v0, 0.f) * w2lo + fmaxf(v1, 0.f) * w2hi;
        ull pp; PACK2(pp, part0, part1);
        #pragma unroll
        for (int off = 16; off; off >>= 1) {
            ull o = __shfl_down_sync(0xffffffffu, pp, off);
            ADD2(pp, pp, o);
        }
        if (lane == 0) {
            UNPACK2(part0, part1, pp);
            float2 r = make_float2(part0 + b2v, part1 + b2v);
            reinterpret_cast<float2*>(out)[pair] = r;
        }
        __syncwarp();
    }
}

extern "C" void kernel_launch(void* const* d_in, const int* in_sizes, int n_in,
                              void* d_out, int out_size)
{
    const float* x    = (const float*)d_in[0];  // [256,1024,1]
    const float* wih0 = (const float*)d_in[1];  // [256,1]
    const float* wihR = (const float*)d_in[2];  // [4,256,64]
    const float* whh  = (const float*)d_in[3];  // [5,256,64]
    const float* bih  = (const float*)d_in[4];  // [5,256]
    const float* bhh  = (const float*)d_in[5];  // [5,256]
    const float* W1   = (const float*)d_in[6];  // [64,64]
    const float* b1   = (const float*)d_in[7];  // [64]
    const float* W2   = (const float*)d_in[8];  // [1,64]
    const float* b2   = (const float*)d_in[9];  // [1]
    float* out = (float*)d_out;                 // [256,1024,1]
    (void)in_sizes; (void)n_in; (void)out_size; // future == 0 per setup

    void *pA = nullptr, *pB = nullptr;
    cudaGetSymbolAddress(&pA, g_bufA);
    cudaGetSymbolAddress(&pB, g_bufB);
    float* bufA = (float*)pA;
    float* bufB = (float*)pB;

    const int WSZ = GG * HH;  // per-layer weight block
    lstm_scan<true ><<<128, 256>>>(x,    wih0,            whh,           bih,          bhh,          bufA);
    lstm_scan<false><<<128, 256>>>(bufA, wihR + 0 * WSZ,  whh + 1 * WSZ, bih + 1 * GG, bhh + 1 * GG, bufB);
    lstm_scan<false><<<128, 256>>>(bufB, wihR + 1 * WSZ,  whh + 2 * WSZ, bih + 2 * GG, bhh + 2 * GG, bufA);
    lstm_scan<false><<<128, 256>>>(bufA, wihR + 2 * WSZ,  whh + 3 * WSZ, bih + 3 * GG, bhh + 3 * GG, bufB);
    lstm_scan<false><<<128, 256>>>(bufB, wihR + 3 * WSZ,  whh + 4 * WSZ, bih + 4 * GG, bhh + 4 * GG, bufA);
    fc_kernel<<<2048, 256>>>(bufA, W1, b1, W2, b2, out);
}

// round 3
// speedup vs baseline: 1.2124x; 1.2124x over previous
#include <cuda_runtime.h>

#define BB 256
#define TT 1024
#define HH 64
#define GG 256   // 4*H gates

// Static device buffers (no allocs): h ping-pong + input-projection buffer.
__device__ float g_bufA[BB * TT * HH];   // 64 MB
__device__ float g_bufB[BB * TT * HH];   // 64 MB
__device__ float g_gx[BB * TT * GG];     // 256 MB

typedef unsigned long long ull;

__device__ __forceinline__ float sigf(float x) {
    x = fminf(fmaxf(x, -30.f), 30.f);
    return 1.0f / (1.0f + __expf(-x));
}
__device__ __forceinline__ float tanhf_fast(float x) {
    x = fminf(fmaxf(x, -15.f), 15.f);
    float e = __expf(-2.0f * x);
    return (1.0f - e) / (1.0f + e);
}

// Blackwell packed fp32 ops (PTX-only).
#define FFMA2(acc, a, b) \
    asm("fma.rn.f32x2 %0, %1, %2, %0;" : "+l"(acc) : "l"(a), "l"(b))
#define ADD2(d, a, b) \
    asm("add.rn.f32x2 %0, %1, %2;" : "=l"(d) : "l"(a), "l"(b))
#define UNPACK2(lo, hi, p) \
    asm("mov.b64 {%0,%1}, %2;" : "=f"(lo), "=f"(hi) : "l"(p))
#define PACK2(p, lo, hi) \
    asm("mov.b64 %0, {%1,%2};" : "=l"(p) : "f"(lo), "f"(hi))

// ---------------------------------------------------------------------------
// Input-projection GEMM: gx[r][g] = h_in[r]·W_ih[g] + b_ih[g] + b_hh[g]
// r = b*1024 + t. CTA b handles its 1024 rows; thread g owns W_ih row g in
// registers; rows staged 4 at a time through smem (double-buffered).
// ---------------------------------------------------------------------------
__global__ void __launch_bounds__(256, 2)
gx_gemm(const float* __restrict__ hin,  // [B,T,64]
        const float* __restrict__ wih,  // [256,64]
        const float* __restrict__ bih,  // [256]
        const float* __restrict__ bhh,  // [256]
        float* __restrict__ gx)         // [B,T,256]
{
    const int g = threadIdx.x;
    ull w2[32];
    {
        const ull* wr = reinterpret_cast<const ull*>(wih + g * 64);
        #pragma unroll
        for (int k = 0; k < 32; k++) w2[k] = wr[k];
    }
    const float bsum = bih[g] + bhh[g];

    __shared__ __align__(16) float buf[2][4][64];  // [slot][row][col]

    const size_t r0 = (size_t)blockIdx.x * TT;
    const int lrow = g >> 6, lcol = g & 63;

    // stage quad 0
    buf[0][lrow][lcol] = hin[(r0 + lrow) * 64 + lcol];
    __syncthreads();

    for (int p = 0; p < TT / 4; ++p) {
        // stage quad p+1 into the other slot
        if (p + 1 < TT / 4)
            buf[(p + 1) & 1][lrow][lcol] =
                hin[(r0 + 4 * (p + 1) + lrow) * 64 + lcol];

        const ulonglong2* r0p = reinterpret_cast<const ulonglong2*>(buf[p & 1][0]);
        const ulonglong2* r1p = reinterpret_cast<const ulonglong2*>(buf[p & 1][1]);
        const ulonglong2* r2p = reinterpret_cast<const ulonglong2*>(buf[p & 1][2]);
        const ulonglong2* r3p = reinterpret_cast<const ulonglong2*>(buf[p & 1][3]);
        ull a0 = 0, a1 = 0, b0 = 0, b1 = 0, c0 = 0, c1 = 0, d0 = 0, d1 = 0;
        #pragma unroll
        for (int k = 0; k < 16; k++) {
            ull wlo = w2[2 * k], whi = w2[2 * k + 1];
            ulonglong2 v0 = r0p[k];
            ulonglong2 v1 = r1p[k];
            ulonglong2 v2 = r2p[k];
            ulonglong2 v3 = r3p[k];
            FFMA2(a0, wlo, v0.x); FFMA2(a1, whi, v0.y);
            FFMA2(b0, wlo, v1.x); FFMA2(b1, whi, v1.y);
            FFMA2(c0, wlo, v2.x); FFMA2(c1, whi, v2.y);
            FFMA2(d0, wlo, v3.x); FFMA2(d1, whi, v3.y);
        }
        float lo, hi;
        size_t out0 = (r0 + 4 * p) * GG + g;
        ADD2(a0, a0, a1); UNPACK2(lo, hi, a0); gx[out0]          = bsum + lo + hi;
        ADD2(b0, b0, b1); UNPACK2(lo, hi, b0); gx[out0 + GG]     = bsum + lo + hi;
        ADD2(c0, c0, c1); UNPACK2(lo, hi, c0); gx[out0 + 2 * GG] = bsum + lo + hi;
        ADD2(d0, d0, d1); UNPACK2(lo, hi, d0); gx[out0 + 3 * GG] = bsum + lo + hi;
        __syncthreads();
    }
}

// ---------------------------------------------------------------------------
// LSTM scan. 256 CTAs x 256 threads, 2 CTAs/SM. CTA owns batch row b.
// Thread g owns gate row g; W_hh row in 64 regs. x-projection comes from gx
// (or inline scalar FMA for the first layer).
// ---------------------------------------------------------------------------
template <bool FIRST>
__global__ void __launch_bounds__(256, 2)
lstm_scan(const float* __restrict__ gxin,  // FIRST: x [B,T]; else gx [B,T,256]
          const float* __restrict__ wih0,  // FIRST only: [256]
          const float* __restrict__ whh,   // [256,64]
          const float* __restrict__ bih,   // FIRST only
          const float* __restrict__ bhh,   // FIRST only
          float* __restrict__ hout)        // [B,T,64]
{
    const int g = threadIdx.x;
    const int b = blockIdx.x;

    __shared__ __align__(16) float hs[64];
    __shared__ float gsm[256];

    ull whh2[32];
    {
        const ull* wr = reinterpret_cast<const ull*>(whh + g * 64);
        #pragma unroll
        for (int k = 0; k < 32; k++) whh2[k] = wr[k];
    }
    float wscal = 0.f, bsum = 0.f;
    if (FIRST) { wscal = wih0[g]; bsum = bih[g] + bhh[g]; }

    if (g < 64) hs[g] = 0.f;
    float c = 0.f;

    const float* gp;
    size_t stride;
    if (FIRST) { gp = gxin + (size_t)b * TT;      stride = 1; }
    else       { gp = gxin + (size_t)b * TT * GG + g; stride = GG; }
    float qa = gp[0];                 // t
    float qb = gp[stride];            // t+1
    __syncthreads();

    for (int t = 0; t < TT; ++t) {
        // issue prefetch for t+2 early; consumed after rotate
        float qc = 0.f;
        if (t + 2 < TT) qc = gp[(size_t)(t + 2) * stride];

        // h-part: 32 FFMA2 in 4 chains (broadcast LDS.128)
        ull h0 = 0, h1 = 0, h2 = 0, h3 = 0;
        const ulonglong2* hv = reinterpret_cast<const ulonglong2*>(hs);
        #pragma unroll
        for (int k = 0; k < 8; k++) {
            ulonglong2 va = hv[2 * k];
            ulonglong2 vb = hv[2 * k + 1];
            FFMA2(h0, whh2[4 * k],     va.x);
            FFMA2(h1, whh2[4 * k + 1], va.y);
            FFMA2(h2, whh2[4 * k + 2], vb.x);
            FFMA2(h3, whh2[4 * k + 3], vb.y);
        }
        ull u, v;
        ADD2(u, h0, h1); ADD2(v, h2, h3); ADD2(u, u, v);
        float lo, hi; UNPACK2(lo, hi, u);
        float a = lo + hi;
        if (FIRST) a += bsum + wscal * qa;
        else       a += qa;

        // gate rows: [0,64) i  [64,128) f  [128,192) g(tanh)  [192,256) o
        float val = (g >= 128 && g < 192) ? tanhf_fast(a) : sigf(a);
        gsm[g] = val;
        qa = qb; qb = qc;
        __syncthreads();

        if (g < 64) {
            float iv = gsm[g];
            float fv = gsm[64 + g];
            float gv = gsm[128 + g];
            float ov = gsm[192 + g];
            c = fv * c + iv * gv;
            float hval = ov * tanhf_fast(c);
            hs[g] = hval;
            hout[((size_t)b * TT + t) * 64 + g] = hval;
        }
        __syncthreads();
    }
}

// ---------------------------------------------------------------------------
// Head: out = relu(relu(h) @ W1^T + b1) @ W2^T + b2 (packed FFMA2).
// ---------------------------------------------------------------------------
__global__ void __launch_bounds__(256)
fc_kernel(const float* __restrict__ hin,  // [B,T,64]
          const float* __restrict__ W1,   // [64,64]
          const float* __restrict__ b1,   // [64]
          const float* __restrict__ W2,   // [1,64]
          const float* __restrict__ b2,   // [1]
          float* __restrict__ out)        // [B*T]
{
    __shared__ ull  W1P[64 * 32];   // (W1[l][k], W1[l+32][k])
    __shared__ float b1s[64];
    __shared__ float w2s[64];
    __shared__ float hsm[8][2][64];

    for (int i = threadIdx.x; i < 64 * 32; i += 256) {
        int k = i >> 5, l = i & 31;
        ull p; PACK2(p, W1[l * 64 + k], W1[(l + 32) * 64 + k]);
        W1P[k * 32 + l] = p;
    }
    if (threadIdx.x < 64) {
        b1s[threadIdx.x] = b1[threadIdx.x];
        w2s[threadIdx.x] = W2[threadIdx.x];
    }
    __syncthreads();
    const float b2v = b2[0];

    const int warp = threadIdx.x >> 5, lane = threadIdx.x & 31;
    ull ybias; PACK2(ybias, b1s[lane], b1s[lane + 32]);
    const float w2lo = w2s[lane], w2hi = w2s[lane + 32];

    const int npairs = BB * TT / 2;
    for (int pair = blockIdx.x * 8 + warp; pair < npairs; pair += gridDim.x * 8) {
        size_t p0 = (size_t)pair * 2;
        float h00 = fmaxf(hin[p0 * 64 + lane], 0.f);
        float h01 = fmaxf(hin[p0 * 64 + 32 + lane], 0.f);
        float h10 = fmaxf(hin[(p0 + 1) * 64 + lane], 0.f);
        float h11 = fmaxf(hin[(p0 + 1) * 64 + 32 + lane], 0.f);
        hsm[warp][0][lane]      = h00;
        hsm[warp][0][lane + 32] = h01;
        hsm[warp][1][lane]      = h10;
        hsm[warp][1][lane + 32] = h11;
        __syncwarp();

        ull y0a = ybias, y0b = 0, y1a = ybias, y1b = 0;
        #pragma unroll
        for (int k = 0; k < 64; k += 2) {
            ull w0 = W1P[k * 32 + lane];
            ull w1 = W1P[(k + 1) * 32 + lane];
            float hv00 = hsm[warp][0][k], hv01 = hsm[warp][0][k + 1];
            float hv10 = hsm[warp][1][k], hv11 = hsm[warp][1][k + 1];
            ull d00; PACK2(d00, hv00, hv00);
            ull d01; PACK2(d01, hv01, hv01);
            ull d10; PACK2(d10, hv10, hv10);
            ull d11; PACK2(d11, hv11, hv11);
            FFMA2(y0a, w0, d00);
            FFMA2(y0b, w1, d01);
            FFMA2(y1a, w0, d10);
            FFMA2(y1b, w1, d11);
        }
        ADD2(y0a, y0a, y0b);
        ADD2(y1a, y1a, y1b);
        float u0, u1, v0, v1;
        UNPACK2(u0, u1, y0a);
        UNPACK2(v0, v1, y1a);
        float part0 = fmaxf(u0, 0.f) * w2lo + fmaxf(u1, 0.f) * w2hi;
        float part1 = fmaxf(v0, 0.f) * w2lo + fmaxf(v1, 0.f) * w2hi;
        ull pp; PACK2(pp, part0, part1);
        #pragma unroll
        for (int off = 16; off; off >>= 1) {
            ull o = __shfl_down_sync(0xffffffffu, pp, off);
            ADD2(pp, pp, o);
        }
        if (lane == 0) {
            UNPACK2(part0, part1, pp);
            reinterpret_cast<float2*>(out)[pair] =
                make_float2(part0 + b2v, part1 + b2v);
        }
        __syncwarp();
    }
}

extern "C" void kernel_launch(void* const* d_in, const int* in_sizes, int n_in,
                              void* d_out, int out_size)
{
    const float* x    = (const float*)d_in[0];  // [256,1024,1]
    const float* wih0 = (const float*)d_in[1];  // [256,1]
    const float* wihR = (const float*)d_in[2];  // [4,256,64]
    const float* whh  = (const float*)d_in[3];  // [5,256,64]
    const float* bih  = (const float*)d_in[4];  // [5,256]
    const float* bhh  = (const float*)d_in[5];  // [5,256]
    const float* W1   = (const float*)d_in[6];  // [64,64]
    const float* b1   = (const float*)d_in[7];  // [64]
    const float* W2   = (const float*)d_in[8];  // [1,64]
    const float* b2   = (const float*)d_in[9];  // [1]
    float* out = (float*)d_out;                 // [256,1024,1]
    (void)in_sizes; (void)n_in; (void)out_size; // future == 0 per setup

    void *pA = nullptr, *pB = nullptr, *pG = nullptr;
    cudaGetSymbolAddress(&pA, g_bufA);
    cudaGetSymbolAddress(&pB, g_bufB);
    cudaGetSymbolAddress(&pG, g_gx);
    float* bufA = (float*)pA;
    float* bufB = (float*)pB;
    float* gx   = (float*)pG;

    const int WSZ = GG * HH;  // per-layer weight block

    // layer 0: x is scalar per step — inline projection
    lstm_scan<true><<<256, 256>>>(x, wih0, whh, bih, bhh, bufA);

    float* cur = bufA;
    float* nxt = bufB;
    for (int l = 1; l < 5; ++l) {
        gx_gemm<<<256, 256>>>(cur, wihR + (l - 1) * WSZ,
                              bih + l * GG, bhh + l * GG, gx);
        lstm_scan<false><<<256, 256>>>(gx, nullptr, whh + l * WSZ,
                                       nullptr, nullptr, nxt);
        float* tmp = cur; cur = nxt; nxt = tmp;
    }
    fc_kernel<<<2048, 256>>>(cur, W1, b1, W2, b2, out);
}